// round 11
// baseline (speedup 1.0000x reference)
#include <cuda_runtime.h>
#include <cuda_bf16.h>
#include <cstdint>

#define BB   256
#define VV   50
#define NPV  32
#define DD   128
#define NDD  4096
#define GG   1560
#define GPAD 1664
#define LL   12
#define HH   384
#define HSS  64
#define CSS  10
#define OUTW 128
#define MBV  12800
#define OUT_ELEMS (BB*OUTW)
#define KCV  (HH*CSS)   /* 3840 */
#define KOUT (VV*HH)    /* 19200 */

// ---------------- scratch ----------------
__device__ __nv_bfloat16 g_Xhi[(long)MBV * NDD];
__device__ __nv_bfloat16 g_Xlo[(long)MBV * NDD];
__device__ __nv_bfloat16 g_WKhi[(long)GPAD * NDD];
__device__ __nv_bfloat16 g_WKlo[(long)GPAD * NDD];
__device__ __nv_bfloat16 g_RWhi[(long)GPAD * HH];
__device__ __nv_bfloat16 g_RWlo[(long)GPAD * HH];
__device__ __nv_bfloat16 g_LHhi[(long)MBV * KCV];
__device__ __nv_bfloat16 g_LHlo[(long)MBV * KCV];
__device__ __nv_bfloat16 g_CWhi[HH * KCV];
__device__ __nv_bfloat16 g_CWlo[HH * KCV];
__device__ __nv_bfloat16 g_hhi[BB * HH];
__device__ __nv_bfloat16 g_hlo[BB * HH];
__device__ float g_bias2[GG];
__device__ float g_tw[GG];
__device__ float g_XO[(long)MBV * GG];
__device__ float g_xo[BB * GG];
__device__ float g_c[BB * HH];
__device__ float g_rh[CSS * BB * HH];
__device__ float g_rd[CSS * BB];
__device__ float g_hall[MBV * HH];
__device__ float g_theme[MBV * HH];
__device__ float g_rnn[BB * KOUT];
__device__ float g_opart[16 * BB * OUTW];

// ---------------- PTX helpers (baseline ISA only) ----------------
__device__ __forceinline__ uint32_t smem_to_u32(const void* p) {
    uint32_t a;
    asm("{ .reg .u64 t; cvta.to.shared.u64 t, %1; cvt.u32.u64 %0, t; }" : "=r"(a) : "l"(p));
    return a;
}
__device__ __forceinline__ void cp_async16(uint32_t dst, const void* src) {
    asm volatile("cp.async.cg.shared.global [%0], [%1], 16;" :: "r"(dst), "l"(src));
}
#define CP_COMMIT() asm volatile("cp.async.commit_group;")
#define CP_WAIT1()  asm volatile("cp.async.wait_group 1;")
#define CP_WAIT0()  asm volatile("cp.async.wait_group 0;")

#define LDSM4(r0, r1, r2, r3, a) \
    asm volatile("ldmatrix.sync.aligned.m8n8.x4.shared.b16 {%0,%1,%2,%3}, [%4];" \
        : "=r"(r0), "=r"(r1), "=r"(r2), "=r"(r3) : "r"(a))
#define LDSM2(r0, r1, a) \
    asm volatile("ldmatrix.sync.aligned.m8n8.x2.shared.b16 {%0,%1}, [%2];" \
        : "=r"(r0), "=r"(r1) : "r"(a))
#define MMA16816(d, a, b) \
    asm volatile("mma.sync.aligned.m16n8k16.row.col.f32.bf16.bf16.f32 " \
        "{%0,%1,%2,%3}, {%4,%5,%6,%7}, {%8,%9}, {%0,%1,%2,%3};" \
        : "+f"((d)[0]), "+f"((d)[1]), "+f"((d)[2]), "+f"((d)[3]) \
        : "r"((a)[0]), "r"((a)[1]), "r"((a)[2]), "r"((a)[3]), "r"((b)[0]), "r"((b)[1]))

__device__ __forceinline__ float sigf(float x) { return 1.0f / (1.0f + expf(-x)); }
__device__ __forceinline__ void bfsplit(float v, unsigned short& h, unsigned short& l) {
    __nv_bfloat16 hb = __float2bfloat16(v);
    float r = v - __bfloat162float(hb);
    __nv_bfloat16 lb = __float2bfloat16(r);
    h = *reinterpret_cast<unsigned short*>(&hb);
    l = *reinterpret_cast<unsigned short*>(&lb);
}

// ---------------- gather + split ----------------
__global__ void k_gather(const int* __restrict__ ids, const float* __restrict__ embed) {
    long i = (long)blockIdx.x * blockDim.x + threadIdx.x;
    if (i >= (long)MBV * 1024) return;
    int m = (int)(i >> 10);
    int r = (int)(i & 1023);
    int n = r >> 5, d4 = r & 31;
    int id = ids[m * NPV + n];
    float4 v = *(const float4*)(embed + (long)id * DD + d4 * 4);
    unsigned short hx, lx, hy, ly, hz, lz, hw, lw;
    bfsplit(v.x, hx, lx); bfsplit(v.y, hy, ly);
    bfsplit(v.z, hz, lz); bfsplit(v.w, hw, lw);
    long base = (long)m * NDD + n * DD + d4 * 4;
    uint2 ph = make_uint2((uint32_t)hx | ((uint32_t)hy << 16), (uint32_t)hz | ((uint32_t)hw << 16));
    uint2 pl = make_uint2((uint32_t)lx | ((uint32_t)ly << 16), (uint32_t)lz | ((uint32_t)lw << 16));
    *(uint2*)(g_Xhi + base) = ph;
    *(uint2*)(g_Xlo + base) = pl;
}

// ---------------- repacks ----------------
__global__ void k_repack_w(const float* __restrict__ kw) {
    long i = (long)blockIdx.x * blockDim.x + threadIdx.x;
    if (i >= (long)GPAD * NDD) return;
    int n = (int)(i >> 12);
    int k = (int)(i & 4095);
    float v = (n < GG) ? kw[(long)n * (NDD + 1) + k] : 0.0f;
    unsigned short h, l;
    bfsplit(v, h, l);
    g_WKhi[i] = *reinterpret_cast<__nv_bfloat16*>(&h);
    g_WKlo[i] = *reinterpret_cast<__nv_bfloat16*>(&l);
}
__global__ void k_prep(const float* __restrict__ kw, const float* __restrict__ rw,
                       const float* __restrict__ kb, const float* __restrict__ rb) {
    int n = blockIdx.x * blockDim.x + threadIdx.x;
    if (n < GG) {
        g_bias2[n] = kb[n] + rb[n];
        g_tw[n] = kw[(long)n * (NDD + 1) + NDD] + rw[n * (HH + 1) + HH];
    }
}
__global__ void k_repack_r(const float* __restrict__ rw) {
    int i = blockIdx.x * blockDim.x + threadIdx.x;
    if (i >= GPAD * HH) return;
    int n = i / HH; int j = i - n * HH;
    float v = (n < GG) ? rw[n * (HH + 1) + j] : 0.0f;
    unsigned short h, l;
    bfsplit(v, h, l);
    g_RWhi[i] = *reinterpret_cast<__nv_bfloat16*>(&h);
    g_RWlo[i] = *reinterpret_cast<__nv_bfloat16*>(&l);
}
__global__ void k_repack_c(const float* __restrict__ cw) {
    int i = blockIdx.x * blockDim.x + threadIdx.x;
    if (i >= HH * KCV) return;
    int o = i / KCV; int r = i - o * KCV;
    int h = r / CSS; int k = r - h * CSS;
    unsigned short hi, lo;
    bfsplit(cw[i], hi, lo);
    int dst = o * KCV + k * HH + h;
    g_CWhi[dst] = *reinterpret_cast<__nv_bfloat16*>(&hi);
    g_CWlo[dst] = *reinterpret_cast<__nv_bfloat16*>(&lo);
}
__global__ void k_init() {
    int i = blockIdx.x * blockDim.x + threadIdx.x;
    if (i < BB * HH) {
        g_c[i] = 0.0f;
        unsigned short z = 0;
        g_hhi[i] = *reinterpret_cast<__nv_bfloat16*>(&z);
        g_hlo[i] = *reinterpret_cast<__nv_bfloat16*>(&z);
    }
    if (i < CSS * BB * HH) g_rh[i] = 0.0f;
    if (i < CSS * BB) g_rd[i] = 0.0f;
}

// ---------------- warp-MMA GEMM core ----------------
// per buffer: 4 tiles of 128 rows x 64 bf16, row stride 72 (144 B, conflict-free ldmatrix)
#define TSZ   18432
#define BUFSZ (4 * TSZ)
#define TG_SMEM (2 * BUFSZ)

__device__ __forceinline__ void mma_chunk(uint32_t base, int wm, int wn, int lane,
                                          float acc[4][4][4]) {
#pragma unroll
    for (int kk = 0; kk < 4; kk++) {
        uint32_t ah[4][4], al[4][4];
#pragma unroll
        for (int mi = 0; mi < 4; mi++) {
            uint32_t arow = wm + mi * 16 + (lane & 15);
            uint32_t acol = kk * 16 + (lane >> 4) * 8;
            uint32_t addr = base + (arow * 72 + acol) * 2;
            LDSM4(ah[mi][0], ah[mi][1], ah[mi][2], ah[mi][3], addr);
            LDSM4(al[mi][0], al[mi][1], al[mi][2], al[mi][3], addr + TSZ);
        }
        uint32_t bh[4][2], bl[4][2];
#pragma unroll
        for (int ni = 0; ni < 4; ni++) {
            uint32_t brow = wn + ni * 8 + (lane & 7);
            uint32_t bcol = kk * 16 + ((lane >> 3) & 1) * 8;
            uint32_t addr = base + 2 * TSZ + (brow * 72 + bcol) * 2;
            LDSM2(bh[ni][0], bh[ni][1], addr);
            LDSM2(bl[ni][0], bl[ni][1], addr + TSZ);
        }
#pragma unroll
        for (int mi = 0; mi < 4; mi++)
#pragma unroll
            for (int ni = 0; ni < 4; ni++) {
                MMA16816(acc[mi][ni], ah[mi], bh[ni]);
                MMA16816(acc[mi][ni], ah[mi], bl[ni]);
                MMA16816(acc[mi][ni], al[mi], bh[ni]);
            }
    }
}

__device__ __forceinline__ void mma_mainloop(uint32_t smb, int tid,
    const __nv_bfloat16* __restrict__ Ahi, const __nv_bfloat16* __restrict__ Alo,
    long lda, long am0,
    const __nv_bfloat16* __restrict__ Bhi, const __nv_bfloat16* __restrict__ Blo,
    long ldb, long bn0, int nchunk, float acc[4][4][4])
{
    const int lane = tid & 31, wid = tid >> 5;
    const int wm = (wid >> 2) * 64, wn = (wid & 3) * 32;

    auto load_chunk = [&](int c, int buf) {
        long kt = (long)c * 64;
        uint32_t base = smb + buf * BUFSZ;
#pragma unroll
        for (int it = 0; it < 4; it++) {
            int idx = tid + it * 256;
            int row = idx >> 3, cg = idx & 7;
            uint32_t off = (uint32_t)(row * 72 + cg * 8) * 2;
            long ka = (am0 + row) * lda + kt + cg * 8;
            long kb = (bn0 + row) * ldb + kt + cg * 8;
            cp_async16(base + off,           Ahi + ka);
            cp_async16(base + TSZ + off,     Alo + ka);
            cp_async16(base + 2 * TSZ + off, Bhi + kb);
            cp_async16(base + 3 * TSZ + off, Blo + kb);
        }
        CP_COMMIT();
    };

    load_chunk(0, 0);
    load_chunk(1, 1);
    for (int c = 0; c < nchunk; c++) {
        if (c + 2 < nchunk) { CP_WAIT1(); } else { CP_WAIT0(); }
        __syncthreads();
        mma_chunk(smb + (c & 1) * BUFSZ, wm, wn, lane, acc);
        __syncthreads();
        if (c + 2 < nchunk) load_chunk(c + 2, c & 1);
    }
}

// ---------------- big GEMM: XO = X @ WK^T + bias2 + time*tw ----------------
__global__ __launch_bounds__(256) void k_mma_big(const float* __restrict__ timev) {
    extern __shared__ char sm[];
    uint32_t smb = smem_to_u32(sm);
    const int tid = threadIdx.x;
    const int m0 = blockIdx.y * 128;
    const int n0 = blockIdx.x * 128;
    float acc[4][4][4];
#pragma unroll
    for (int mi = 0; mi < 4; mi++)
#pragma unroll
        for (int ni = 0; ni < 4; ni++)
#pragma unroll
            for (int q = 0; q < 4; q++) acc[mi][ni][q] = 0.0f;

    mma_mainloop(smb, tid, g_Xhi, g_Xlo, NDD, m0, g_WKhi, g_WKlo, NDD, n0, NDD / 64, acc);

    const int lane = tid & 31, wid = tid >> 5;
    const int wm = (wid >> 2) * 64, wn = (wid & 3) * 32;
#pragma unroll
    for (int mi = 0; mi < 4; mi++) {
        int r0 = m0 + wm + mi * 16 + (lane >> 2);
        int r8 = r0 + 8;
        float tv0 = timev[r0], tv8 = timev[r8];
#pragma unroll
        for (int ni = 0; ni < 4; ni++) {
            int col = n0 + wn + ni * 8 + (lane & 3) * 2;
            if (col < GG) {
                float b0 = g_bias2[col], b1 = g_bias2[col + 1];
                float w0 = g_tw[col], w1 = g_tw[col + 1];
                g_XO[(long)r0 * GG + col]     = acc[mi][ni][0] + b0 + tv0 * w0;
                g_XO[(long)r0 * GG + col + 1] = acc[mi][ni][1] + b1 + tv0 * w1;
                g_XO[(long)r8 * GG + col]     = acc[mi][ni][2] + b0 + tv8 * w0;
                g_XO[(long)r8 * GG + col + 1] = acc[mi][ni][3] + b1 + tv8 * w1;
            }
        }
    }
}

// ---------------- conv GEMM: rnn = theme*(LH@CW^T + cb) + hall ----------------
__global__ __launch_bounds__(256) void k_mma_conv(const float* __restrict__ cb) {
    extern __shared__ char sm[];
    uint32_t smb = smem_to_u32(sm);
    const int tid = threadIdx.x;
    const int m0 = blockIdx.y * 128;   // m = t*B+b
    const int n0 = blockIdx.x * 128;   // o
    float acc[4][4][4];
#pragma unroll
    for (int mi = 0; mi < 4; mi++)
#pragma unroll
        for (int ni = 0; ni < 4; ni++)
#pragma unroll
            for (int q = 0; q < 4; q++) acc[mi][ni][q] = 0.0f;

    mma_mainloop(smb, tid, g_LHhi, g_LHlo, KCV, m0, g_CWhi, g_CWlo, KCV, n0, KCV / 64, acc);

    const int lane = tid & 31, wid = tid >> 5;
    const int wm = (wid >> 2) * 64, wn = (wid & 3) * 32;
#pragma unroll
    for (int mi = 0; mi < 4; mi++) {
        int r0 = m0 + wm + mi * 16 + (lane >> 2);
        int r8 = r0 + 8;
        int b0r = r0 & 255, t0r = r0 >> 8;
        int b8r = r8 & 255, t8r = r8 >> 8;
#pragma unroll
        for (int ni = 0; ni < 4; ni++) {
            int col = n0 + wn + ni * 8 + (lane & 3) * 2;
            float cb0 = cb[col], cb1 = cb[col + 1];
            long s0 = (long)r0 * HH + col;
            long s8 = (long)r8 * HH + col;
            long d0 = (long)b0r * KOUT + (long)t0r * HH + col;
            long d8 = (long)b8r * KOUT + (long)t8r * HH + col;
            g_rnn[d0]     = g_theme[s0]     * (acc[mi][ni][0] + cb0) + g_hall[s0];
            g_rnn[d0 + 1] = g_theme[s0 + 1] * (acc[mi][ni][1] + cb1) + g_hall[s0 + 1];
            g_rnn[d8]     = g_theme[s8]     * (acc[mi][ni][2] + cb0) + g_hall[s8];
            g_rnn[d8 + 1] = g_theme[s8 + 1] * (acc[mi][ni][3] + cb1) + g_hall[s8 + 1];
        }
    }
}

// ---------------- per-step recurrent GEMM (HMMA): xo = XO[.,t] + h @ RW^T ----------------
__global__ __launch_bounds__(256) void k_recgemm(int t) {
    extern __shared__ char sm[];
    uint32_t smb = smem_to_u32(sm);
    const int tid = threadIdx.x;
    const int m0 = blockIdx.y * 128;   // b
    const int n0 = blockIdx.x * 128;   // g
    float acc[4][4][4];
#pragma unroll
    for (int mi = 0; mi < 4; mi++)
#pragma unroll
        for (int ni = 0; ni < 4; ni++)
#pragma unroll
            for (int q = 0; q < 4; q++) acc[mi][ni][q] = 0.0f;

    mma_mainloop(smb, tid, g_hhi, g_hlo, HH, m0, g_RWhi, g_RWlo, HH, n0, HH / 64, acc);

    const int lane = tid & 31, wid = tid >> 5;
    const int wm = (wid >> 2) * 64, wn = (wid & 3) * 32;
#pragma unroll
    for (int mi = 0; mi < 4; mi++) {
        int r0 = m0 + wm + mi * 16 + (lane >> 2);
        int r8 = r0 + 8;
#pragma unroll
        for (int ni = 0; ni < 4; ni++) {
            int col = n0 + wn + ni * 8 + (lane & 3) * 2;
            if (col < GG) {
                g_xo[r0 * GG + col]     = acc[mi][ni][0] + g_XO[((long)r0 * VV + t) * GG + col];
                g_xo[r0 * GG + col + 1] = acc[mi][ni][1] + g_XO[((long)r0 * VV + t) * GG + col + 1];
                g_xo[r8 * GG + col]     = acc[mi][ni][2] + g_XO[((long)r8 * VV + t) * GG + col];
                g_xo[r8 * GG + col + 1] = acc[mi][ni][3] + g_XO[((long)r8 * VV + t) * GG + col + 1];
            }
        }
    }
}

// ---------------- gates + window + theme ----------------
__global__ __launch_bounds__(128) void k_gates(int t,
        const float* __restrict__ sw, const float* __restrict__ sb,
        const float* __restrict__ rw, const float* __restrict__ rb2,
        float* __restrict__ dout) {
    const int b = blockIdx.x;
    const int tid = threadIdx.x;
    __shared__ float s_fm[LL], s_im[LL], s_ld[CSS], s_wh[HH], s_s1[HSS];
    const float* xo = g_xo + b * GG;
    const int slot = t % CSS;

    if (tid == 0) {
        float x[LL], mx = -1e30f;
        for (int l = 0; l < LL; l++) { x[l] = xo[l]; mx = fmaxf(mx, x[l]); }
        float s = 0.0f;
        for (int l = 0; l < LL; l++) { x[l] = expf(x[l] - mx); s += x[l]; }
        float inv = 1.0f / s, cum = 0.0f, fmsum = 0.0f;
        for (int l = 0; l < LL; l++) { cum += x[l] * inv; s_fm[l] = cum; fmsum += cum; }
        float dist = 1.0f - fmsum * (1.0f / LL);
        g_rd[slot * BB + b] = dist;
        dout[OUT_ELEMS + t * BB + b] = dist;
        mx = -1e30f;
        for (int l = 0; l < LL; l++) { x[l] = xo[LL + l]; mx = fmaxf(mx, x[l]); }
        s = 0.0f;
        for (int l = 0; l < LL; l++) { x[l] = expf(x[l] - mx); s += x[l]; }
        inv = 1.0f / s; cum = 0.0f;
        for (int l = LL - 1; l >= 0; l--) { cum += x[l] * inv; s_im[l] = cum; }
    }
    __syncthreads();

    for (int e = tid; e < HH; e += 128) {
        int l = e >> 5;
        float f  = sigf(xo[24 + e]);
        float ii = sigf(xo[24 + HH + e]);
        float oo = sigf(xo[24 + 2 * HH + e]);
        float ci = tanhf(xo[24 + 3 * HH + e]);
        float cl = g_c[b * HH + e];
        float fm = s_fm[l], im = s_im[l], ov = fm * im;
        float cn = ov * (f * cl + ii * ci) + (fm - ov) * cl + (im - ov) * ci;
        float hn = oo * tanhf(cn);
        g_c[b * HH + e] = cn;
        unsigned short hs, ls;
        bfsplit(hn, hs, ls);
        g_hhi[b * HH + e] = *reinterpret_cast<__nv_bfloat16*>(&hs);
        g_hlo[b * HH + e] = *reinterpret_cast<__nv_bfloat16*>(&ls);
        g_rh[(slot * BB + b) * HH + e] = hn;
        g_hall[((long)t * BB + b) * HH + e] = hn;
    }
    __syncthreads();

    if (tid == 0) {
        float tmp[CSS], cum = 0.0f, mx = -1e30f;
        for (int p = 0; p < CSS; p++) {
            int sp = (t + 1 + p) % CSS;
            cum += g_rd[sp * BB + b];
            tmp[p] = cum;
            mx = fmaxf(mx, cum);
        }
        float s = 0.0f;
        for (int p = 0; p < CSS; p++) { tmp[p] = expf(tmp[p] - mx); s += tmp[p]; }
        float inv = 1.0f / s;
        for (int p = 0; p < CSS; p++) s_ld[p] = tmp[p] * inv;
    }
    __syncthreads();

    __nv_bfloat16* LHh = g_LHhi + ((long)t * BB + b) * KCV;
    __nv_bfloat16* LHl = g_LHlo + ((long)t * BB + b) * KCV;
    for (int e = tid; e < HH; e += 128) {
        float accv = 0.0f;
#pragma unroll
        for (int p = 0; p < CSS; p++) {
            int sp = (t + 1 + p) % CSS;
            float v = g_rh[(sp * BB + b) * HH + e] * s_ld[p];
            unsigned short h, l;
            bfsplit(v, h, l);
            LHh[p * HH + e] = *reinterpret_cast<__nv_bfloat16*>(&h);
            LHl[p * HH + e] = *reinterpret_cast<__nv_bfloat16*>(&l);
            accv += v;
        }
        s_wh[e] = accv * (1.0f / CSS);
    }
    __syncthreads();

    if (tid < HSS) {
        float a = sb[tid];
        const float* wr = sw + tid * HH;
        for (int h = 0; h < HH; h++) a += s_wh[h] * wr[h];
        s_s1[tid] = fmaxf(a, 0.0f);
    }
    __syncthreads();

    for (int e = tid; e < HH; e += 128) {
        float a = rb2[e];
        const float* wr2 = rw + e * HSS;
#pragma unroll 8
        for (int j = 0; j < HSS; j++) a += s_s1[j] * wr2[j];
        g_theme[((long)t * BB + b) * HH + e] = sigf(a);
    }
}

// ---------------- f32x2 SIMT helpers ----------------
__device__ __forceinline__ double pk2(float lo, float hi) {
    double r; asm("mov.b64 %0,{%1,%2};" : "=d"(r) : "f"(lo), "f"(hi)); return r;
}
__device__ __forceinline__ void fma2(double& c, double a, double b) {
    asm("fma.rn.f32x2 %0,%1,%2,%0;" : "+d"(c) : "d"(a), "d"(b));
}
__device__ __forceinline__ float2 upk(double d) {
    float2 f; asm("mov.b64 {%0,%1},%2;" : "=f"(f.x), "=f"(f.y) : "d"(d)); return f;
}

// ---------------- out GEMM split-K ----------------
__global__ __launch_bounds__(256) void k_out(const float* __restrict__ ow) {
    const int m0 = blockIdx.x * 64;
    const int n0 = blockIdx.y * 64;
    const int ks = blockIdx.z * 1200;
    __shared__ __align__(16) float As[16][68];
    __shared__ __align__(16) float Ws[16][68];
    const int tid = threadIdx.x;
    const int tx = tid & 15, ty = tid >> 4;
    double acc[4][2];
#pragma unroll
    for (int r = 0; r < 4; r++) { acc[r][0] = 0.0; acc[r][1] = 0.0; }

    for (int kt = 0; kt < 1200; kt += 16) {
        int row = tid >> 2;
        int kc = (tid & 3) * 4;
        float4 av = *(const float4*)(g_rnn + (long)(m0 + row) * KOUT + ks + kt + kc);
        As[kc + 0][row] = av.x; As[kc + 1][row] = av.y;
        As[kc + 2][row] = av.z; As[kc + 3][row] = av.w;
        float4 wv = *(const float4*)(ow + (long)(n0 + row) * KOUT + ks + kt + kc);
        Ws[kc + 0][row] = wv.x; Ws[kc + 1][row] = wv.y;
        Ws[kc + 2][row] = wv.z; Ws[kc + 3][row] = wv.w;
        __syncthreads();
#pragma unroll
        for (int k = 0; k < 16; k++) {
            float4 a = *(const float4*)&As[k][ty * 4];
            double2 w = *(const double2*)&Ws[k][tx * 4];
            float ar[4] = {a.x, a.y, a.z, a.w};
#pragma unroll
            for (int r = 0; r < 4; r++) {
                double pa = pk2(ar[r], ar[r]);
                fma2(acc[r][0], pa, w.x); fma2(acc[r][1], pa, w.y);
            }
        }
        __syncthreads();
    }
    const int sp = blockIdx.z;
#pragma unroll
    for (int r = 0; r < 4; r++) {
        int m = m0 + ty * 4 + r;
#pragma unroll
        for (int c = 0; c < 2; c++) {
            int n = n0 + tx * 4 + 2 * c;
            float2 v = upk(acc[r][c]);
            g_opart[(sp * BB + m) * OUTW + n]     = v.x;
            g_opart[(sp * BB + m) * OUTW + n + 1] = v.y;
        }
    }
}

__global__ void k_outred(const float* __restrict__ ob, float* __restrict__ out) {
    int i = blockIdx.x * blockDim.x + threadIdx.x;
    if (i >= BB * OUTW) return;
    int b = i >> 7, o = i & 127;
    float s = ob[o];
#pragma unroll
    for (int sp = 0; sp < 16; sp++) s += g_opart[(sp * BB + b) * OUTW + o];
    out[i] = s;
}

extern "C" void kernel_launch(void* const* d_in, const int* in_sizes, int n_in,
                              void* d_out, int out_size) {
    const int*   node_ids = (const int*)  d_in[0];
    const float* timev    = (const float*)d_in[3];
    const float* embed    = (const float*)d_in[6];
    const float* kernel_w = (const float*)d_in[7];
    const float* kernel_b = (const float*)d_in[8];
    const float* rec_w    = (const float*)d_in[9];
    const float* rec_b    = (const float*)d_in[10];
    const float* scale_w  = (const float*)d_in[11];
    const float* scale_b  = (const float*)d_in[12];
    const float* rescale_w= (const float*)d_in[13];
    const float* rescale_b= (const float*)d_in[14];
    const float* conv_w   = (const float*)d_in[15];
    const float* conv_b   = (const float*)d_in[16];
    const float* out_w    = (const float*)d_in[17];
    const float* out_b    = (const float*)d_in[18];
    float* out = (float*)d_out;

    cudaFuncSetAttribute(k_mma_big,  cudaFuncAttributeMaxDynamicSharedMemorySize, TG_SMEM);
    cudaFuncSetAttribute(k_mma_conv, cudaFuncAttributeMaxDynamicSharedMemorySize, TG_SMEM);
    cudaFuncSetAttribute(k_recgemm,  cudaFuncAttributeMaxDynamicSharedMemorySize, TG_SMEM);

    // launch order chosen so k_mma_big is the 4th launch (ncu captures index 3)
    k_gather<<<(MBV * 1024 + 255) / 256, 256>>>(node_ids, embed);
    k_repack_w<<<(int)(((long)GPAD * NDD + 255) / 256), 256>>>(kernel_w);
    k_prep<<<(GG + 255) / 256, 256>>>(kernel_w, rec_w, kernel_b, rec_b);
    k_mma_big<<<dim3(GPAD / 128, MBV / 128), 256, TG_SMEM>>>(timev);

    k_repack_r<<<(GPAD * HH + 255) / 256, 256>>>(rec_w);
    k_repack_c<<<(HH * KCV + 255) / 256, 256>>>(conv_w);
    k_init<<<(CSS * BB * HH + 255) / 256, 256>>>();

    for (int t = 0; t < VV; t++) {
        k_recgemm<<<dim3(GPAD / 128, BB / 128), 256, TG_SMEM>>>(t);
        k_gates<<<BB, 128>>>(t, scale_w, scale_b, rescale_w, rescale_b, out);
    }

    k_mma_conv<<<dim3(HH / 128, MBV / 128), 256, TG_SMEM>>>(conv_b);

    dim3 go(BB / 64, OUTW / 64, 16);
    k_out<<<go, 256>>>(out_w);
    k_outred<<<(BB * OUTW + 255) / 256, 256>>>(out_b, out);
}

// round 14
// speedup vs baseline: 1.1308x; 1.1308x over previous
#include <cuda_runtime.h>
#include <cuda_bf16.h>
#include <cstdint>

#define BB   256
#define VV   50
#define NPV  32
#define DD   128
#define NDD  4096
#define GG   1560
#define GPAD 1664
#define LL   12
#define HH   384
#define HSS  64
#define CSS  10
#define OUTW 128
#define MBV  12800
#define OUT_ELEMS (BB*OUTW)
#define KCV  (HH*CSS)   /* 3840 */
#define KOUT (VV*HH)    /* 19200 */

// ---------------- scratch ----------------
__device__ __nv_bfloat16 g_Xhi[(long)MBV * NDD];
__device__ __nv_bfloat16 g_Xlo[(long)MBV * NDD];
__device__ __nv_bfloat16 g_WKhi[(long)GPAD * NDD];
__device__ __nv_bfloat16 g_WKlo[(long)GPAD * NDD];
__device__ __nv_bfloat16 g_RWhi[(long)GPAD * HH];
__device__ __nv_bfloat16 g_RWlo[(long)GPAD * HH];
__device__ __nv_bfloat16 g_LHhi[(long)MBV * KCV];
__device__ __nv_bfloat16 g_LHlo[(long)MBV * KCV];
__device__ __nv_bfloat16 g_CWhi[HH * KCV];
__device__ __nv_bfloat16 g_CWlo[HH * KCV];
__device__ __nv_bfloat16 g_hhi[BB * HH];
__device__ __nv_bfloat16 g_hlo[BB * HH];
__device__ float g_bias2[GG];
__device__ float g_tw[GG];
__device__ float g_XO[(long)MBV * GG];
__device__ float g_xo[BB * GG];
__device__ float g_c[BB * HH];
__device__ float g_rh[CSS * BB * HH];
__device__ float g_rd[CSS * BB];
__device__ float g_hall[MBV * HH];
__device__ float g_theme[MBV * HH];
__device__ float g_rnn[BB * KOUT];
__device__ float g_opart[16 * BB * OUTW];

// ---------------- PTX helpers (baseline ISA only) ----------------
__device__ __forceinline__ uint32_t smem_to_u32(const void* p) {
    uint32_t a;
    asm("{ .reg .u64 t; cvta.to.shared.u64 t, %1; cvt.u32.u64 %0, t; }" : "=r"(a) : "l"(p));
    return a;
}
__device__ __forceinline__ void cp_async16(uint32_t dst, const void* src) {
    asm volatile("cp.async.cg.shared.global [%0], [%1], 16;" :: "r"(dst), "l"(src));
}
#define CP_COMMIT() asm volatile("cp.async.commit_group;")
#define CP_WAIT1()  asm volatile("cp.async.wait_group 1;")
#define CP_WAIT0()  asm volatile("cp.async.wait_group 0;")

#define LDSM4(r0, r1, r2, r3, a) \
    asm volatile("ldmatrix.sync.aligned.m8n8.x4.shared.b16 {%0,%1,%2,%3}, [%4];" \
        : "=r"(r0), "=r"(r1), "=r"(r2), "=r"(r3) : "r"(a))
#define LDSM2(r0, r1, a) \
    asm volatile("ldmatrix.sync.aligned.m8n8.x2.shared.b16 {%0,%1}, [%2];" \
        : "=r"(r0), "=r"(r1) : "r"(a))
#define MMA16816(d, a, b) \
    asm volatile("mma.sync.aligned.m16n8k16.row.col.f32.bf16.bf16.f32 " \
        "{%0,%1,%2,%3}, {%4,%5,%6,%7}, {%8,%9}, {%0,%1,%2,%3};" \
        : "+f"((d)[0]), "+f"((d)[1]), "+f"((d)[2]), "+f"((d)[3]) \
        : "r"((a)[0]), "r"((a)[1]), "r"((a)[2]), "r"((a)[3]), "r"((b)[0]), "r"((b)[1]))

__device__ __forceinline__ float sigf(float x) { return 1.0f / (1.0f + expf(-x)); }
__device__ __forceinline__ void bfsplit(float v, unsigned short& h, unsigned short& l) {
    __nv_bfloat16 hb = __float2bfloat16(v);
    float r = v - __bfloat162float(hb);
    __nv_bfloat16 lb = __float2bfloat16(r);
    h = *reinterpret_cast<unsigned short*>(&hb);
    l = *reinterpret_cast<unsigned short*>(&lb);
}

// ---------------- gather + split ----------------
__global__ void k_gather(const int* __restrict__ ids, const float* __restrict__ embed) {
    long i = (long)blockIdx.x * blockDim.x + threadIdx.x;
    if (i >= (long)MBV * 1024) return;
    int m = (int)(i >> 10);
    int r = (int)(i & 1023);
    int n = r >> 5, d4 = r & 31;
    int id = ids[m * NPV + n];
    float4 v = *(const float4*)(embed + (long)id * DD + d4 * 4);
    unsigned short hx, lx, hy, ly, hz, lz, hw, lw;
    bfsplit(v.x, hx, lx); bfsplit(v.y, hy, ly);
    bfsplit(v.z, hz, lz); bfsplit(v.w, hw, lw);
    long base = (long)m * NDD + n * DD + d4 * 4;
    uint2 ph = make_uint2((uint32_t)hx | ((uint32_t)hy << 16), (uint32_t)hz | ((uint32_t)hw << 16));
    uint2 pl = make_uint2((uint32_t)lx | ((uint32_t)ly << 16), (uint32_t)lz | ((uint32_t)lw << 16));
    *(uint2*)(g_Xhi + base) = ph;
    *(uint2*)(g_Xlo + base) = pl;
}

// ---------------- repacks ----------------
__global__ void k_repack_w(const float* __restrict__ kw) {
    long i = (long)blockIdx.x * blockDim.x + threadIdx.x;
    if (i >= (long)GPAD * NDD) return;
    int n = (int)(i >> 12);
    int k = (int)(i & 4095);
    float v = (n < GG) ? kw[(long)n * (NDD + 1) + k] : 0.0f;
    unsigned short h, l;
    bfsplit(v, h, l);
    g_WKhi[i] = *reinterpret_cast<__nv_bfloat16*>(&h);
    g_WKlo[i] = *reinterpret_cast<__nv_bfloat16*>(&l);
}
__global__ void k_prep(const float* __restrict__ kw, const float* __restrict__ rw,
                       const float* __restrict__ kb, const float* __restrict__ rb) {
    int n = blockIdx.x * blockDim.x + threadIdx.x;
    if (n < GG) {
        g_bias2[n] = kb[n] + rb[n];
        g_tw[n] = kw[(long)n * (NDD + 1) + NDD] + rw[n * (HH + 1) + HH];
    }
}
__global__ void k_repack_r(const float* __restrict__ rw) {
    int i = blockIdx.x * blockDim.x + threadIdx.x;
    if (i >= GPAD * HH) return;
    int n = i / HH; int j = i - n * HH;
    float v = (n < GG) ? rw[n * (HH + 1) + j] : 0.0f;
    unsigned short h, l;
    bfsplit(v, h, l);
    g_RWhi[i] = *reinterpret_cast<__nv_bfloat16*>(&h);
    g_RWlo[i] = *reinterpret_cast<__nv_bfloat16*>(&l);
}
__global__ void k_repack_c(const float* __restrict__ cw) {
    int i = blockIdx.x * blockDim.x + threadIdx.x;
    if (i >= HH * KCV) return;
    int o = i / KCV; int r = i - o * KCV;
    int h = r / CSS; int k = r - h * CSS;
    unsigned short hi, lo;
    bfsplit(cw[i], hi, lo);
    int dst = o * KCV + k * HH + h;
    g_CWhi[dst] = *reinterpret_cast<__nv_bfloat16*>(&hi);
    g_CWlo[dst] = *reinterpret_cast<__nv_bfloat16*>(&lo);
}
__global__ void k_init() {
    int i = blockIdx.x * blockDim.x + threadIdx.x;
    if (i < BB * HH) {
        g_c[i] = 0.0f;
        unsigned short z = 0;
        g_hhi[i] = *reinterpret_cast<__nv_bfloat16*>(&z);
        g_hlo[i] = *reinterpret_cast<__nv_bfloat16*>(&z);
    }
    if (i < CSS * BB * HH) g_rh[i] = 0.0f;
    if (i < CSS * BB) g_rd[i] = 0.0f;
}

// ---------------- warp-MMA GEMM core (128x128, K-chunk 32, 2 CTA/SM) ----------------
// per buffer: 4 tiles of 128 rows x 32 bf16, row stride 40 halfwords (80B, conflict-free)
#define TSZ   10240
#define BUFSZ (4 * TSZ)
#define TG_SMEM (2 * BUFSZ)   /* 81920 -> 2 CTAs/SM */

__device__ __forceinline__ void mma_chunk(uint32_t base, int wm, int wn, int lane,
                                          float acc[4][4][4]) {
#pragma unroll
    for (int kk = 0; kk < 2; kk++) {
        uint32_t ah[4][4], al[4][4];
#pragma unroll
        for (int mi = 0; mi < 4; mi++) {
            uint32_t arow = wm + mi * 16 + (lane & 15);
            uint32_t acol = kk * 16 + (lane >> 4) * 8;
            uint32_t addr = base + (arow * 40 + acol) * 2;
            LDSM4(ah[mi][0], ah[mi][1], ah[mi][2], ah[mi][3], addr);
            LDSM4(al[mi][0], al[mi][1], al[mi][2], al[mi][3], addr + TSZ);
        }
        uint32_t bh[4][2], bl[4][2];
#pragma unroll
        for (int ni = 0; ni < 4; ni++) {
            uint32_t brow = wn + ni * 8 + (lane & 7);
            uint32_t bcol = kk * 16 + ((lane >> 3) & 1) * 8;
            uint32_t addr = base + 2 * TSZ + (brow * 40 + bcol) * 2;
            LDSM2(bh[ni][0], bh[ni][1], addr);
            LDSM2(bl[ni][0], bl[ni][1], addr + TSZ);
        }
#pragma unroll
        for (int mi = 0; mi < 4; mi++)
#pragma unroll
            for (int ni = 0; ni < 4; ni++) {
                MMA16816(acc[mi][ni], ah[mi], bh[ni]);
                MMA16816(acc[mi][ni], ah[mi], bl[ni]);
                MMA16816(acc[mi][ni], al[mi], bh[ni]);
            }
    }
}

__device__ __forceinline__ void mma_mainloop(uint32_t smb, int tid,
    const __nv_bfloat16* __restrict__ Ahi, const __nv_bfloat16* __restrict__ Alo,
    long lda, long am0,
    const __nv_bfloat16* __restrict__ Bhi, const __nv_bfloat16* __restrict__ Blo,
    long ldb, long bn0, int nchunk, float acc[4][4][4])
{
    const int lane = tid & 31, wid = tid >> 5;
    const int wm = (wid >> 2) * 64, wn = (wid & 3) * 32;

    auto load_chunk = [&](int c, int buf) {
        long kt = (long)c * 32;
        uint32_t base = smb + buf * BUFSZ;
#pragma unroll
        for (int it = 0; it < 2; it++) {
            int idx = tid + it * 256;
            int row = idx >> 2, cg = idx & 3;
            uint32_t off = (uint32_t)(row * 40 + cg * 8) * 2;
            long ka = (am0 + row) * lda + kt + cg * 8;
            long kb = (bn0 + row) * ldb + kt + cg * 8;
            cp_async16(base + off,           Ahi + ka);
            cp_async16(base + TSZ + off,     Alo + ka);
            cp_async16(base + 2 * TSZ + off, Bhi + kb);
            cp_async16(base + 3 * TSZ + off, Blo + kb);
        }
        CP_COMMIT();
    };

    load_chunk(0, 0);
    load_chunk(1, 1);
    for (int c = 0; c < nchunk; c++) {
        if (c + 2 < nchunk) { CP_WAIT1(); } else { CP_WAIT0(); }
        __syncthreads();
        mma_chunk(smb + (c & 1) * BUFSZ, wm, wn, lane, acc);
        __syncthreads();
        if (c + 2 < nchunk) load_chunk(c + 2, c & 1);
    }
}

// ---------------- big GEMM: XO = X @ WK^T + bias2 + time*tw ----------------
__global__ __launch_bounds__(256, 2) void k_mma_big(const float* __restrict__ timev) {
    extern __shared__ char sm[];
    uint32_t smb = smem_to_u32(sm);
    const int tid = threadIdx.x;
    const int m0 = blockIdx.y * 128;
    const int n0 = blockIdx.x * 128;
    float acc[4][4][4];
#pragma unroll
    for (int mi = 0; mi < 4; mi++)
#pragma unroll
        for (int ni = 0; ni < 4; ni++)
#pragma unroll
            for (int q = 0; q < 4; q++) acc[mi][ni][q] = 0.0f;

    mma_mainloop(smb, tid, g_Xhi, g_Xlo, NDD, m0, g_WKhi, g_WKlo, NDD, n0, NDD / 32, acc);

    const int lane = tid & 31, wid = tid >> 5;
    const int wm = (wid >> 2) * 64, wn = (wid & 3) * 32;
#pragma unroll
    for (int mi = 0; mi < 4; mi++) {
        int r0 = m0 + wm + mi * 16 + (lane >> 2);
        int r8 = r0 + 8;
        float tv0 = timev[r0], tv8 = timev[r8];
#pragma unroll
        for (int ni = 0; ni < 4; ni++) {
            int col = n0 + wn + ni * 8 + (lane & 3) * 2;
            if (col < GG) {
                float b0 = g_bias2[col], b1 = g_bias2[col + 1];
                float w0 = g_tw[col], w1 = g_tw[col + 1];
                g_XO[(long)r0 * GG + col]     = acc[mi][ni][0] + b0 + tv0 * w0;
                g_XO[(long)r0 * GG + col + 1] = acc[mi][ni][1] + b1 + tv0 * w1;
                g_XO[(long)r8 * GG + col]     = acc[mi][ni][2] + b0 + tv8 * w0;
                g_XO[(long)r8 * GG + col + 1] = acc[mi][ni][3] + b1 + tv8 * w1;
            }
        }
    }
}

// ---------------- conv GEMM: rnn = theme*(LH@CW^T + cb) + hall ----------------
__global__ __launch_bounds__(256, 2) void k_mma_conv(const float* __restrict__ cb) {
    extern __shared__ char sm[];
    uint32_t smb = smem_to_u32(sm);
    const int tid = threadIdx.x;
    const int m0 = blockIdx.y * 128;   // m = t*B+b
    const int n0 = blockIdx.x * 128;   // o
    float acc[4][4][4];
#pragma unroll
    for (int mi = 0; mi < 4; mi++)
#pragma unroll
        for (int ni = 0; ni < 4; ni++)
#pragma unroll
            for (int q = 0; q < 4; q++) acc[mi][ni][q] = 0.0f;

    mma_mainloop(smb, tid, g_LHhi, g_LHlo, KCV, m0, g_CWhi, g_CWlo, KCV, n0, KCV / 32, acc);

    const int lane = tid & 31, wid = tid >> 5;
    const int wm = (wid >> 2) * 64, wn = (wid & 3) * 32;
#pragma unroll
    for (int mi = 0; mi < 4; mi++) {
        int r0 = m0 + wm + mi * 16 + (lane >> 2);
        int r8 = r0 + 8;
        int b0r = r0 & 255, t0r = r0 >> 8;
        int b8r = r8 & 255, t8r = r8 >> 8;
#pragma unroll
        for (int ni = 0; ni < 4; ni++) {
            int col = n0 + wn + ni * 8 + (lane & 3) * 2;
            float cb0 = cb[col], cb1 = cb[col + 1];
            long s0 = (long)r0 * HH + col;
            long s8 = (long)r8 * HH + col;
            long d0 = (long)b0r * KOUT + (long)t0r * HH + col;
            long d8 = (long)b8r * KOUT + (long)t8r * HH + col;
            g_rnn[d0]     = g_theme[s0]     * (acc[mi][ni][0] + cb0) + g_hall[s0];
            g_rnn[d0 + 1] = g_theme[s0 + 1] * (acc[mi][ni][1] + cb1) + g_hall[s0 + 1];
            g_rnn[d8]     = g_theme[s8]     * (acc[mi][ni][2] + cb0) + g_hall[s8];
            g_rnn[d8 + 1] = g_theme[s8 + 1] * (acc[mi][ni][3] + cb1) + g_hall[s8 + 1];
        }
    }
}

// ---------------- per-step recurrent GEMM (HMMA, 64x64 tiles, 104 CTAs) ----------------
// smem per buffer: 4 tiles of 64 rows x 32 bf16 stride 40 -> 5120 B each
#define RTSZ   5120
#define RBUFSZ (4 * RTSZ)

__global__ __launch_bounds__(256) void k_recgemm(int t) {
    __shared__ __align__(16) char sm[2 * RBUFSZ];  // 40 KB static
    uint32_t smb = smem_to_u32(sm);
    const int tid = threadIdx.x;
    const int lane = tid & 31, wid = tid >> 5;
    const int n0 = blockIdx.x * 64;   // g
    const int m0 = blockIdx.y * 64;   // b
    const int wm = (wid >> 2) * 32, wn = (wid & 3) * 16;
    float acc[2][2][4];
#pragma unroll
    for (int mi = 0; mi < 2; mi++)
#pragma unroll
        for (int ni = 0; ni < 2; ni++)
#pragma unroll
            for (int q = 0; q < 4; q++) acc[mi][ni][q] = 0.0f;

    auto load_chunk = [&](int c, int buf) {
        int kt = c * 32;
        uint32_t base = smb + buf * RBUFSZ;
        int row = tid >> 2, cg = tid & 3;            // 64 rows x 4 groups = 256
        uint32_t off = (uint32_t)(row * 40 + cg * 8) * 2;
        long ka = (long)(m0 + row) * HH + kt + cg * 8;
        long kb = (long)(n0 + row) * HH + kt + cg * 8;
        cp_async16(base + off,            g_hhi + ka);
        cp_async16(base + RTSZ + off,     g_hlo + ka);
        cp_async16(base + 2 * RTSZ + off, g_RWhi + kb);
        cp_async16(base + 3 * RTSZ + off, g_RWlo + kb);
        CP_COMMIT();
    };

    const int nchunk = HH / 32;  // 12
    load_chunk(0, 0);
    load_chunk(1, 1);
    for (int c = 0; c < nchunk; c++) {
        if (c + 2 < nchunk) { CP_WAIT1(); } else { CP_WAIT0(); }
        __syncthreads();
        uint32_t base = smb + (c & 1) * RBUFSZ;
#pragma unroll
        for (int kk = 0; kk < 2; kk++) {
            uint32_t ah[2][4], al[2][4];
#pragma unroll
            for (int mi = 0; mi < 2; mi++) {
                uint32_t arow = wm + mi * 16 + (lane & 15);
                uint32_t acol = kk * 16 + (lane >> 4) * 8;
                uint32_t addr = base + (arow * 40 + acol) * 2;
                LDSM4(ah[mi][0], ah[mi][1], ah[mi][2], ah[mi][3], addr);
                LDSM4(al[mi][0], al[mi][1], al[mi][2], al[mi][3], addr + RTSZ);
            }
            uint32_t bh[2][2], bl[2][2];
#pragma unroll
            for (int ni = 0; ni < 2; ni++) {
                uint32_t brow = wn + ni * 8 + (lane & 7);
                uint32_t bcol = kk * 16 + ((lane >> 3) & 1) * 8;
                uint32_t addr = base + 2 * RTSZ + (brow * 40 + bcol) * 2;
                LDSM2(bh[ni][0], bh[ni][1], addr);
                LDSM2(bl[ni][0], bl[ni][1], addr + RTSZ);
            }
#pragma unroll
            for (int mi = 0; mi < 2; mi++)
#pragma unroll
                for (int ni = 0; ni < 2; ni++) {
                    MMA16816(acc[mi][ni], ah[mi], bh[ni]);
                    MMA16816(acc[mi][ni], ah[mi], bl[ni]);
                    MMA16816(acc[mi][ni], al[mi], bh[ni]);
                }
        }
        __syncthreads();
        if (c + 2 < nchunk) load_chunk(c + 2, c & 1);
    }

#pragma unroll
    for (int mi = 0; mi < 2; mi++) {
        int r0 = m0 + wm + mi * 16 + (lane >> 2);
        int r8 = r0 + 8;
#pragma unroll
        for (int ni = 0; ni < 2; ni++) {
            int col = n0 + wn + ni * 8 + (lane & 3) * 2;
            if (col < GG) {
                g_xo[r0 * GG + col]     = acc[mi][ni][0] + g_XO[((long)r0 * VV + t) * GG + col];
                g_xo[r0 * GG + col + 1] = acc[mi][ni][1] + g_XO[((long)r0 * VV + t) * GG + col + 1];
                g_xo[r8 * GG + col]     = acc[mi][ni][2] + g_XO[((long)r8 * VV + t) * GG + col];
                g_xo[r8 * GG + col + 1] = acc[mi][ni][3] + g_XO[((long)r8 * VV + t) * GG + col + 1];
            }
        }
    }
}

// ---------------- gates + window + theme ----------------
__global__ __launch_bounds__(128) void k_gates(int t,
        const float* __restrict__ sw, const float* __restrict__ sb,
        const float* __restrict__ rw, const float* __restrict__ rb2,
        float* __restrict__ dout) {
    const int b = blockIdx.x;
    const int tid = threadIdx.x;
    __shared__ float s_fm[LL], s_im[LL], s_ld[CSS], s_wh[HH], s_s1[HSS];
    const float* xo = g_xo + b * GG;
    const int slot = t % CSS;

    if (tid == 0) {
        float x[LL], mx = -1e30f;
        for (int l = 0; l < LL; l++) { x[l] = xo[l]; mx = fmaxf(mx, x[l]); }
        float s = 0.0f;
        for (int l = 0; l < LL; l++) { x[l] = expf(x[l] - mx); s += x[l]; }
        float inv = 1.0f / s, cum = 0.0f, fmsum = 0.0f;
        for (int l = 0; l < LL; l++) { cum += x[l] * inv; s_fm[l] = cum; fmsum += cum; }
        float dist = 1.0f - fmsum * (1.0f / LL);
        g_rd[slot * BB + b] = dist;
        dout[OUT_ELEMS + t * BB + b] = dist;
        mx = -1e30f;
        for (int l = 0; l < LL; l++) { x[l] = xo[LL + l]; mx = fmaxf(mx, x[l]); }
        s = 0.0f;
        for (int l = 0; l < LL; l++) { x[l] = expf(x[l] - mx); s += x[l]; }
        inv = 1.0f / s; cum = 0.0f;
        for (int l = LL - 1; l >= 0; l--) { cum += x[l] * inv; s_im[l] = cum; }
    }
    __syncthreads();

    for (int e = tid; e < HH; e += 128) {
        int l = e >> 5;
        float f  = sigf(xo[24 + e]);
        float ii = sigf(xo[24 + HH + e]);
        float oo = sigf(xo[24 + 2 * HH + e]);
        float ci = tanhf(xo[24 + 3 * HH + e]);
        float cl = g_c[b * HH + e];
        float fm = s_fm[l], im = s_im[l], ov = fm * im;
        float cn = ov * (f * cl + ii * ci) + (fm - ov) * cl + (im - ov) * ci;
        float hn = oo * tanhf(cn);
        g_c[b * HH + e] = cn;
        unsigned short hs, ls;
        bfsplit(hn, hs, ls);
        g_hhi[b * HH + e] = *reinterpret_cast<__nv_bfloat16*>(&hs);
        g_hlo[b * HH + e] = *reinterpret_cast<__nv_bfloat16*>(&ls);
        g_rh[(slot * BB + b) * HH + e] = hn;
        g_hall[((long)t * BB + b) * HH + e] = hn;
    }
    __syncthreads();

    if (tid == 0) {
        float tmp[CSS], cum = 0.0f, mx = -1e30f;
        for (int p = 0; p < CSS; p++) {
            int sp = (t + 1 + p) % CSS;
            cum += g_rd[sp * BB + b];
            tmp[p] = cum;
            mx = fmaxf(mx, cum);
        }
        float s = 0.0f;
        for (int p = 0; p < CSS; p++) { tmp[p] = expf(tmp[p] - mx); s += tmp[p]; }
        float inv = 1.0f / s;
        for (int p = 0; p < CSS; p++) s_ld[p] = tmp[p] * inv;
    }
    __syncthreads();

    __nv_bfloat16* LHh = g_LHhi + ((long)t * BB + b) * KCV;
    __nv_bfloat16* LHl = g_LHlo + ((long)t * BB + b) * KCV;
    for (int e = tid; e < HH; e += 128) {
        float accv = 0.0f;
#pragma unroll
        for (int p = 0; p < CSS; p++) {
            int sp = (t + 1 + p) % CSS;
            float v = g_rh[(sp * BB + b) * HH + e] * s_ld[p];
            unsigned short h, l;
            bfsplit(v, h, l);
            LHh[p * HH + e] = *reinterpret_cast<__nv_bfloat16*>(&h);
            LHl[p * HH + e] = *reinterpret_cast<__nv_bfloat16*>(&l);
            accv += v;
        }
        s_wh[e] = accv * (1.0f / CSS);
    }
    __syncthreads();

    if (tid < HSS) {
        float a = sb[tid];
        const float* wr = sw + tid * HH;
        for (int h = 0; h < HH; h++) a += s_wh[h] * wr[h];
        s_s1[tid] = fmaxf(a, 0.0f);
    }
    __syncthreads();

    for (int e = tid; e < HH; e += 128) {
        float a = rb2[e];
        const float* wr2 = rw + e * HSS;
#pragma unroll 8
        for (int j = 0; j < HSS; j++) a += s_s1[j] * wr2[j];
        g_theme[((long)t * BB + b) * HH + e] = sigf(a);
    }
}

// ---------------- f32x2 SIMT helpers ----------------
__device__ __forceinline__ double pk2(float lo, float hi) {
    double r; asm("mov.b64 %0,{%1,%2};" : "=d"(r) : "f"(lo), "f"(hi)); return r;
}
__device__ __forceinline__ void fma2(double& c, double a, double b) {
    asm("fma.rn.f32x2 %0,%1,%2,%0;" : "+d"(c) : "d"(a), "d"(b));
}
__device__ __forceinline__ float2 upk(double d) {
    float2 f; asm("mov.b64 {%0,%1},%2;" : "=f"(f.x), "=f"(f.y) : "d"(d)); return f;
}

// ---------------- out GEMM split-K ----------------
__global__ __launch_bounds__(256) void k_out(const float* __restrict__ ow) {
    const int m0 = blockIdx.x * 64;
    const int n0 = blockIdx.y * 64;
    const int ks = blockIdx.z * 1200;
    __shared__ __align__(16) float As[16][68];
    __shared__ __align__(16) float Ws[16][68];
    const int tid = threadIdx.x;
    const int tx = tid & 15, ty = tid >> 4;
    double acc[4][2];
#pragma unroll
    for (int r = 0; r < 4; r++) { acc[r][0] = 0.0; acc[r][1] = 0.0; }

    for (int kt = 0; kt < 1200; kt += 16) {
        int row = tid >> 2;
        int kc = (tid & 3) * 4;
        float4 av = *(const float4*)(g_rnn + (long)(m0 + row) * KOUT + ks + kt + kc);
        As[kc + 0][row] = av.x; As[kc + 1][row] = av.y;
        As[kc + 2][row] = av.z; As[kc + 3][row] = av.w;
        float4 wv = *(const float4*)(ow + (long)(n0 + row) * KOUT + ks + kt + kc);
        Ws[kc + 0][row] = wv.x; Ws[kc + 1][row] = wv.y;
        Ws[kc + 2][row] = wv.z; Ws[kc + 3][row] = wv.w;
        __syncthreads();
#pragma unroll
        for (int k = 0; k < 16; k++) {
            float4 a = *(const float4*)&As[k][ty * 4];
            double2 w = *(const double2*)&Ws[k][tx * 4];
            float ar[4] = {a.x, a.y, a.z, a.w};
#pragma unroll
            for (int r = 0; r < 4; r++) {
                double pa = pk2(ar[r], ar[r]);
                fma2(acc[r][0], pa, w.x); fma2(acc[r][1], pa, w.y);
            }
        }
        __syncthreads();
    }
    const int sp = blockIdx.z;
#pragma unroll
    for (int r = 0; r < 4; r++) {
        int m = m0 + ty * 4 + r;
#pragma unroll
        for (int c = 0; c < 2; c++) {
            int n = n0 + tx * 4 + 2 * c;
            float2 v = upk(acc[r][c]);
            g_opart[(sp * BB + m) * OUTW + n]     = v.x;
            g_opart[(sp * BB + m) * OUTW + n + 1] = v.y;
        }
    }
}

__global__ void k_outred(const float* __restrict__ ob, float* __restrict__ out) {
    int i = blockIdx.x * blockDim.x + threadIdx.x;
    if (i >= BB * OUTW) return;
    int b = i >> 7, o = i & 127;
    float s = ob[o];
#pragma unroll
    for (int sp = 0; sp < 16; sp++) s += g_opart[(sp * BB + b) * OUTW + o];
    out[i] = s;
}

extern "C" void kernel_launch(void* const* d_in, const int* in_sizes, int n_in,
                              void* d_out, int out_size) {
    const int*   node_ids = (const int*)  d_in[0];
    const float* timev    = (const float*)d_in[3];
    const float* embed    = (const float*)d_in[6];
    const float* kernel_w = (const float*)d_in[7];
    const float* kernel_b = (const float*)d_in[8];
    const float* rec_w    = (const float*)d_in[9];
    const float* rec_b    = (const float*)d_in[10];
    const float* scale_w  = (const float*)d_in[11];
    const float* scale_b  = (const float*)d_in[12];
    const float* rescale_w= (const float*)d_in[13];
    const float* rescale_b= (const float*)d_in[14];
    const float* conv_w   = (const float*)d_in[15];
    const float* conv_b   = (const float*)d_in[16];
    const float* out_w    = (const float*)d_in[17];
    const float* out_b    = (const float*)d_in[18];
    float* out = (float*)d_out;

    cudaFuncSetAttribute(k_mma_big,  cudaFuncAttributeMaxDynamicSharedMemorySize, TG_SMEM);
    cudaFuncSetAttribute(k_mma_conv, cudaFuncAttributeMaxDynamicSharedMemorySize, TG_SMEM);

    // launch order chosen so k_mma_big is the 4th launch (ncu capture slot)
    k_gather<<<(MBV * 1024 + 255) / 256, 256>>>(node_ids, embed);
    k_repack_w<<<(int)(((long)GPAD * NDD + 255) / 256), 256>>>(kernel_w);
    k_prep<<<(GG + 255) / 256, 256>>>(kernel_w, rec_w, kernel_b, rec_b);
    k_mma_big<<<dim3(GPAD / 128, MBV / 128), 256, TG_SMEM>>>(timev);

    k_repack_r<<<(GPAD * HH + 255) / 256, 256>>>(rec_w);
    k_repack_c<<<(HH * KCV + 255) / 256, 256>>>(conv_w);
    k_init<<<(CSS * BB * HH + 255) / 256, 256>>>();

    for (int t = 0; t < VV; t++) {
        k_recgemm<<<dim3(GPAD / 64, BB / 64), 256>>>(t);
        k_gates<<<BB, 128>>>(t, scale_w, scale_b, rescale_w, rescale_b, out);
    }

    k_mma_conv<<<dim3(HH / 128, MBV / 128), 256, TG_SMEM>>>(conv_b);

    dim3 go(BB / 64, OUTW / 64, 16);
    k_out<<<go, 256>>>(out_w);
    k_outred<<<(BB * OUTW + 255) / 256, 256>>>(out_b, out);
}